// round 15
// baseline (speedup 1.0000x reference)
#include <cuda_runtime.h>
#include <math.h>

#define BB   64
#define HH   256
#define TT   512
#define TL   64
#define NCLS 20
#define NSLOT 576   // 512 text + 64 label time slots

// ---------------- device state ----------------
__device__ float4 g_xt[TT*64*64];    // text  x: [t][kq][b]
__device__ float4 g_xl[TL*64*64];    // label x
__device__ float4 g_hpf[TT*64*64];   // premise fw h
__device__ float4 g_hpb[TT*64*64];
__device__ float4 g_hlf[TL*64*64];
__device__ float4 g_hlb[TL*64*64];
__device__ float4 g_hap[3*4*64*64];  // agg h mod-3: [phase][scan][q][b]
__device__ float  g_xp[(size_t)2*NSLOT*1024*64];  // x@Wih^T: [dir][slot][gaterow][b]
__device__ float  g_mvp[TT*2*64];
__device__ float  g_mvh[TL*2*64];
__device__ float  g_y1[512*64];
__device__ unsigned g_cflag[128];
__device__ unsigned g_clflag[128];
__device__ unsigned g_apflag[128];
__device__ unsigned g_ahflag[128];
__device__ unsigned g_xpflag[2*NSLOT];   // per (dir,slot) tile counter (16 = ready)

__device__ __forceinline__ float sigf(float x) { return 1.f / (1.f + __expf(-x)); }

__device__ __forceinline__ unsigned ldacq(const unsigned* p) {
    unsigned v;
    asm volatile("ld.acquire.gpu.u32 %0, [%1];" : "=r"(v) : "l"(p) : "memory");
    return v;
}
__device__ __forceinline__ void strel(unsigned* p, unsigned v) {
    asm volatile("st.release.gpu.u32 [%0], %1;" :: "l"(p), "r"(v) : "memory");
}
__device__ __forceinline__ void atomAddRel(unsigned* p, unsigned v) {
    unsigned old;
    asm volatile("atom.add.release.gpu.u32 %0, [%1], %2;" : "=r"(old) : "l"(p), "r"(v) : "memory");
}

__device__ __forceinline__ float lstm_update(float a0, float a1, float a2, float a3, float &c)
{
    float ig = sigf(a0), fg = sigf(a1), gv = tanhf(a2), og = sigf(a3);
    c = fg * c + ig * gv;
    return og * tanhf(c);
}

// 4-gate GEMV over 64 quads; warp-uniform jj -> weight LDS broadcast (1 wf).
__device__ __forceinline__ void gate_acc64(const float* __restrict__ sW,
                                           const float4* __restrict__ sX,
                                           int jj, int b,
                                           float &a0, float &a1, float &a2, float &a3)
{
    const float* w0 = sW + (jj * 4 + 0) * 256;
    const float* w1 = sW + (jj * 4 + 1) * 256;
    const float* w2 = sW + (jj * 4 + 2) * 256;
    const float* w3 = sW + (jj * 4 + 3) * 256;
    #pragma unroll 4
    for (int q = 0; q < 64; q++) {
        float4 x  = sX[q * 64 + b];
        float4 v0 = *(const float4*)(w0 + q * 4);
        float4 v1 = *(const float4*)(w1 + q * 4);
        float4 v2 = *(const float4*)(w2 + q * 4);
        float4 v3 = *(const float4*)(w3 + q * 4);
        a0 += v0.x * x.x + v0.y * x.y + v0.z * x.z + v0.w * x.w;
        a1 += v1.x * x.x + v1.y * x.y + v1.z * x.z + v1.w * x.w;
        a2 += v2.x * x.x + v2.y * x.y + v2.z * x.z + v2.w * x.w;
        a3 += v3.x * x.x + v3.y * x.y + v3.z * x.z + v3.w * x.w;
    }
}

// ---------------- gather x = emb[tokens]; block 0 zeroes all flags ----------------
__global__ void gather_kernel(const int* __restrict__ text, const int* __restrict__ label,
                              const float* __restrict__ emb)
{
    extern __shared__ float sS[];   // [256][65]
    int tt  = blockIdx.x;
    int tid = threadIdx.x, w = tid >> 5, l = tid & 31;

    if (tt == 0) {
        if (tid < 128) {
            g_cflag[tid] = 0u; g_clflag[tid] = 0u; g_apflag[tid] = 0u; g_ahflag[tid] = 0u;
        }
        for (int i = tid; i < 2 * NSLOT; i += 256) g_xpflag[i] = 0u;
    }

    const int* toks; int T, t; float4* dst;
    if (tt < TT) { toks = text;  T = TT; t = tt;      dst = g_xt; }
    else         { toks = label; T = TL; t = tt - TT; dst = g_xl; }

    for (int bt = w; bt < 64; bt += 8) {
        int tok = toks[bt * T + t];
        const float4* row = (const float4*)(emb + (size_t)tok * 256);
        float4 v0 = row[l], v1 = row[l + 32];
        int k0 = l * 4, k1 = (l + 32) * 4;
        sS[(k0 + 0) * 65 + bt] = v0.x; sS[(k0 + 1) * 65 + bt] = v0.y;
        sS[(k0 + 2) * 65 + bt] = v0.z; sS[(k0 + 3) * 65 + bt] = v0.w;
        sS[(k1 + 0) * 65 + bt] = v1.x; sS[(k1 + 1) * 65 + bt] = v1.y;
        sS[(k1 + 2) * 65 + bt] = v1.z; sS[(k1 + 3) * 65 + bt] = v1.w;
    }
    __syncthreads();
    #pragma unroll
    for (int ii = 0; ii < 16; ii++) {
        int idx = ii * 256 + tid;
        int q = idx >> 6, b = idx & 63;
        float4 o = make_float4(sS[(4*q + 0) * 65 + b], sS[(4*q + 1) * 65 + b],
                               sS[(4*q + 2) * 65 + b], sS[(4*q + 3) * 65 + b]);
        dst[((size_t)t * 64 + q) * 64 + b] = o;
    }
}

// ---------------- fused ctx: CTAs 0..127 scan, CTAs 128..255 produce xproj ----------------
// xproj tiles produced in deadline order; per-(dir,slot) counter flag gates the scan.
__global__ __launch_bounds__(256, 2) void ctx_fused(
    const float* __restrict__ Wih_f, const float* __restrict__ Wih_b,
    const float* __restrict__ Whh_f, const float* __restrict__ bih_f, const float* __restrict__ bhh_f,
    const float* __restrict__ Whh_b, const float* __restrict__ bih_b, const float* __restrict__ bhh_b)
{
    extern __shared__ float sm[];
    int cta = blockIdx.x;
    int tid = threadIdx.x;

    if (cta >= 128) {
        // ================= xproj producer =================
        int p = cta - 128;
        float* sWp = sm;                       // [64 rows][256 k] = 64KB
        int b = tid & 63, jj = tid >> 6;
        for (int it = p; it < 18432; it += 128) {
            int e = it >> 4, rtile = it & 15;
            int dir, slot;
            if (e < 256) {
                int t = e >> 2, k = e & 3;
                if (k == 0)      { dir = 0; slot = t; }
                else if (k == 1) { dir = 1; slot = 511 - t; }
                else if (k == 2) { dir = 0; slot = 512 + t; }
                else             { dir = 1; slot = 512 + 63 - t; }
            } else {
                int e2 = e - 256, t = 64 + (e2 >> 1);
                if ((e2 & 1) == 0) { dir = 0; slot = t; }
                else               { dir = 1; slot = 511 - t; }
            }
            const float* W = dir ? Wih_b : Wih_f;
            #pragma unroll
            for (int ii = 0; ii < 16; ii++) {        // stage W tile: 64 rows x 256 k
                int idx = ii * 256 + tid;
                int r = idx >> 6, k4 = idx & 63;
                *(float4*)&sWp[r * 256 + k4 * 4] =
                    *(const float4*)&W[(size_t)(rtile * 64 + r) * 256 + k4 * 4];
            }
            __syncthreads();
            const float4* xs = (slot < TT) ? (g_xt + (size_t)slot * 4096)
                                           : (g_xl + (size_t)(slot - TT) * 4096);
            float acc[16];
            #pragma unroll
            for (int i = 0; i < 16; i++) acc[i] = 0.f;
            const float* wb = sWp + (jj * 16) * 256;
            #pragma unroll 4
            for (int kq = 0; kq < 64; kq++) {
                float4 x = __ldg(&xs[kq * 64 + b]);
                #pragma unroll
                for (int i = 0; i < 16; i++) {
                    float4 w = *(const float4*)(wb + i * 256 + kq * 4);
                    acc[i] += w.x * x.x + w.y * x.y + w.z * x.z + w.w * x.w;
                }
            }
            size_t base = ((size_t)(dir * NSLOT + slot) * 1024 + rtile * 64 + jj * 16) * 64 + b;
            #pragma unroll
            for (int i = 0; i < 16; i++) g_xp[base + (size_t)i * 64] = acc[i];
            __syncthreads();
            if (tid == 0) atomAddRel(&g_xpflag[dir * NSLOT + slot], 1u);
        }
        return;
    }

    // ================= persistent context scan (proven R6/R12 structure) =================
    float*  sTmp = sm;                           // 256
    float*  sW   = sm + 256;                     // [16][256]
    float4* sH   = (float4*)(sm + 256 + 4096);   // [64 q][64 b]

    int dir = cta >> 6, qc = cta & 63, j0 = qc * 4;
    const float* Whh = dir ? Whh_b : Whh_f;
    const float* bih = dir ? bih_b : bih_f;
    const float* bhh = dir ? bhh_b : bhh_f;
    float4* hT = dir ? g_hpb : g_hpf;
    float4* hL = dir ? g_hlb : g_hlf;

    int b = tid & 63, jj = tid >> 6, j = j0 + jj;

    for (int i = tid; i < 1024; i += 256) {      // stage Whh slice once
        int r = i >> 6, k = (i & 63) * 4;
        int gr = (r & 3) * 256 + j0 + (r >> 2);
        *(float4*)&sW[r * 256 + k] = *(const float4*)&Whh[(size_t)gr * 256 + k];
    }
    float bb0 = bih[j]       + bhh[j];
    float bb1 = bih[256 + j] + bhh[256 + j];
    float bb2 = bih[512 + j] + bhh[512 + j];
    float bb3 = bih[768 + j] + bhh[768 + j];

    float cT = 0.f, cL = 0.f;
    const size_t xpd = (size_t)dir * NSLOT * 65536;   // 1024*64 per slot

    for (int t = 0; t < TT; t++) {
        int pos  = dir ? (TT - 1 - t) : t;
        int posL = dir ? (TL - 1 - t) : t;       // valid when t < TL

        // wait for xproj readiness (text + label), and prev h
        if (tid == 0) {
            const unsigned* f = &g_xpflag[dir * NSLOT + pos];
            while (ldacq(f) < 16u) { }
        }
        if (t < TL && tid == 32) {
            const unsigned* f = &g_xpflag[dir * NSLOT + TT + posL];
            while (ldacq(f) < 16u) { }
        }
        if (t > 0 && tid < 64) {
            const unsigned* f = &g_cflag[dir * 64 + tid];
            while (ldacq(f) < (unsigned)t) { }
        }
        __syncthreads();

        // ---- text sub-step ----
        size_t xb = xpd + (size_t)pos * 65536;
        float xp0 = g_xp[xb + (size_t)(j      ) * 64 + b];
        float xp1 = g_xp[xb + (size_t)(256 + j) * 64 + b];
        float xp2 = g_xp[xb + (size_t)(512 + j) * 64 + b];
        float xp3 = g_xp[xb + (size_t)(768 + j) * 64 + b];
        float a0 = xp0 + bb0, a1 = xp1 + bb1, a2 = xp2 + bb2, a3 = xp3 + bb3;
        if (t > 0) {
            int pp = dir ? pos + 1 : pos - 1;
            const float4* src = hT + (size_t)pp * 4096;
            #pragma unroll
            for (int ii = 0; ii < 16; ii++) { int idx = ii * 256 + tid; sH[idx] = src[idx]; }
            __syncthreads();
            gate_acc64(sW, sH, jj, b, a0, a1, a2, a3);
        }
        float h = lstm_update(a0, a1, a2, a3, cT);
        sTmp[b * 4 + jj] = h;
        __syncthreads();
        if (tid < 64) hT[(size_t)pos * 4096 + qc * 64 + tid] = *(float4*)&sTmp[tid * 4];
        __syncthreads();
        if (tid == 0) strel(&g_cflag[cta], (unsigned)(t + 1));

        // ---- label rides along (t < TL) ----
        if (t < TL) {
            size_t xbl = xpd + (size_t)(TT + posL) * 65536;
            float y0 = g_xp[xbl + (size_t)(j      ) * 64 + b];
            float y1 = g_xp[xbl + (size_t)(256 + j) * 64 + b];
            float y2 = g_xp[xbl + (size_t)(512 + j) * 64 + b];
            float y3 = g_xp[xbl + (size_t)(768 + j) * 64 + b];
            if (t > 0 && tid < 64) {
                const unsigned* f = &g_clflag[dir * 64 + tid];
                while (ldacq(f) < (unsigned)t) { }
            }
            __syncthreads();
            float e0 = y0 + bb0, e1 = y1 + bb1, e2 = y2 + bb2, e3 = y3 + bb3;
            if (t > 0) {
                int ppL = dir ? posL + 1 : posL - 1;
                const float4* src = hL + (size_t)ppL * 4096;
                #pragma unroll
                for (int ii = 0; ii < 16; ii++) { int idx = ii * 256 + tid; sH[idx] = src[idx]; }
                __syncthreads();
                gate_acc64(sW, sH, jj, b, e0, e1, e2, e3);
            }
            float hh = lstm_update(e0, e1, e2, e3, cL);
            sTmp[b * 4 + jj] = hh;
            __syncthreads();
            if (tid < 64) hL[(size_t)posL * 4096 + qc * 64 + tid] = *(float4*)&sTmp[tid * 4];
            __syncthreads();
            if (tid == 0) strel(&g_clflag[cta], (unsigned)(t + 1));
        }
    }
}

// ---------------- multi-perspective match (L = 1), 4 slots per block ----------------
__global__ void match_kernel(const float* __restrict__ w1, const float* __restrict__ w2)
{
    int tid = threadIdx.x;
    int b   = tid & 63;
    int bi  = blockIdx.x * 4 + (tid >> 6);
    const float4 *v1f, *v2f, *v1b, *v2b;
    float* outp;
    if (bi < TT) {
        int t = bi;
        v1f = g_hpf + (size_t)t * 4096;
        v2f = g_hlf + (size_t)(TL - 1) * 4096;
        v1b = g_hpb + (size_t)t * 4096;
        v2b = g_hlb;
        outp = g_mvp + (size_t)t * 2 * 64;
    } else {
        int t = bi - TT;
        v1f = g_hlf + (size_t)t * 4096;
        v2f = g_hpf + (size_t)(TT - 1) * 4096;
        v1b = g_hlb + (size_t)t * 4096;
        v2b = g_hpb;
        outp = g_mvh + (size_t)t * 2 * 64;
    }
    const float4* w14 = (const float4*)w1;
    const float4* w24 = (const float4*)w2;
    float n1 = 0, da = 0, db = 0, n2 = 0, ea = 0, eb = 0;
    for (int q = 0; q < 64; q++) {
        float4 wv = w14[q];
        float4 p = v1f[q * 64 + b], qq = v2f[q * 64 + b];
        float w2x = wv.x*wv.x, w2y = wv.y*wv.y, w2z = wv.z*wv.z, w2w = wv.w*wv.w;
        n1 += w2x*p.x*qq.x + w2y*p.y*qq.y + w2z*p.z*qq.z + w2w*p.w*qq.w;
        da += w2x*p.x*p.x  + w2y*p.y*p.y  + w2z*p.z*p.z  + w2w*p.w*p.w;
        db += w2x*qq.x*qq.x+ w2y*qq.y*qq.y+ w2z*qq.z*qq.z+ w2w*qq.w*qq.w;
        float4 uv = w24[q];
        float4 r = v1b[q * 64 + b], s = v2b[q * 64 + b];
        float u2x = uv.x*uv.x, u2y = uv.y*uv.y, u2z = uv.z*uv.z, u2w = uv.w*uv.w;
        n2 += u2x*r.x*s.x + u2y*r.y*s.y + u2z*r.z*s.z + u2w*r.w*s.w;
        ea += u2x*r.x*r.x + u2y*r.y*r.y + u2z*r.z*r.z + u2w*r.w*r.w;
        eb += u2x*s.x*s.x + u2y*s.y*s.y + u2z*s.z*s.z + u2w*s.w*s.w;
    }
    outp[b]      = n1 / fmaxf(sqrtf(da) * sqrtf(db), 1e-8f);
    outp[64 + b] = n2 / fmaxf(sqrtf(ea) * sqrtf(eb), 1e-8f);
}

// ---------------- persistent aggregation scan (premise + hyp rides t<64) ----------------
__global__ __launch_bounds__(256, 1) void agg_scan(
    const float* __restrict__ Wih_f, const float* __restrict__ Whh_f,
    const float* __restrict__ bih_f, const float* __restrict__ bhh_f,
    const float* __restrict__ Wih_b, const float* __restrict__ Whh_b,
    const float* __restrict__ bih_b, const float* __restrict__ bhh_b)
{
    extern __shared__ float sm[];
    float*  sTmp = sm;
    float*  sW   = sm + 256;
    float4* sH   = (float4*)(sm + 256 + 4096);

    int cta = blockIdx.x, dir = cta >> 6, qc = cta & 63, j0 = qc * 4;
    const float* Wih = dir ? Wih_b : Wih_f;
    const float* Whh = dir ? Whh_b : Whh_f;
    const float* bih = dir ? bih_b : bih_f;
    const float* bhh = dir ? bhh_b : bhh_f;

    int tid = threadIdx.x, b = tid & 63, jj = tid >> 6, j = j0 + jj;

    for (int i = tid; i < 1024; i += 256) {
        int r = i >> 6, k = (i & 63) * 4;
        int gr = (r & 3) * 256 + j0 + (r >> 2);
        *(float4*)&sW[r * 256 + k] = *(const float4*)&Whh[(size_t)gr * 256 + k];
    }
    int r0 = j, r1 = 256 + j, r2 = 512 + j, r3 = 768 + j;
    float bb0 = bih[r0] + bhh[r0], bb1 = bih[r1] + bhh[r1];
    float bb2 = bih[r2] + bhh[r2], bb3 = bih[r3] + bhh[r3];
    float wi00 = Wih[r0*2], wi01 = Wih[r0*2+1];
    float wi10 = Wih[r1*2], wi11 = Wih[r1*2+1];
    float wi20 = Wih[r2*2], wi21 = Wih[r2*2+1];
    float wi30 = Wih[r3*2], wi31 = Wih[r3*2+1];

    float cP = 0.f, cH = 0.f;

    for (int t = 0; t < TT; t++) {
        int wph = t % 3;
        int rph = (t + 2) % 3;

        int pos = dir ? (TT - 1 - t) : t;
        const float* mv = g_mvp + (size_t)pos * 2 * 64;
        float m0 = mv[b], m1 = mv[64 + b];
        if (t > 0 && tid < 64) {
            const unsigned* f = &g_apflag[dir * 64 + tid];
            while (ldacq(f) < (unsigned)t) { }
        }
        __syncthreads();
        float a0 = bb0 + m0 * wi00 + m1 * wi01;
        float a1 = bb1 + m0 * wi10 + m1 * wi11;
        float a2 = bb2 + m0 * wi20 + m1 * wi21;
        float a3 = bb3 + m0 * wi30 + m1 * wi31;
        if (t > 0) {
            const float4* src = g_hap + ((size_t)rph * 4 + dir) * 4096;
            #pragma unroll
            for (int ii = 0; ii < 16; ii++) {
                int idx = ii * 256 + tid;
                sH[idx] = __ldcg(src + idx);
            }
            __syncthreads();
            gate_acc64(sW, sH, jj, b, a0, a1, a2, a3);
        }
        float h = lstm_update(a0, a1, a2, a3, cP);
        sTmp[b * 4 + jj] = h;
        __syncthreads();
        if (tid < 64)
            g_hap[((size_t)wph * 4 + dir) * 4096 + qc * 64 + tid] = *(float4*)&sTmp[tid * 4];
        __syncthreads();
        if (tid == 0) strel(&g_apflag[cta], (unsigned)(t + 1));

        if (t < TL) {
            int posH = dir ? (TL - 1 - t) : t;
            const float* mvh = g_mvh + (size_t)posH * 2 * 64;
            float n0 = mvh[b], n1v = mvh[64 + b];
            if (t > 0 && tid < 64) {
                const unsigned* f = &g_ahflag[dir * 64 + tid];
                while (ldacq(f) < (unsigned)t) { }
            }
            __syncthreads();
            float e0 = bb0 + n0 * wi00 + n1v * wi01;
            float e1 = bb1 + n0 * wi10 + n1v * wi11;
            float e2 = bb2 + n0 * wi20 + n1v * wi21;
            float e3 = bb3 + n0 * wi30 + n1v * wi31;
            if (t > 0) {
                const float4* src = g_hap + ((size_t)rph * 4 + 2 + dir) * 4096;
                #pragma unroll
                for (int ii = 0; ii < 16; ii++) {
                    int idx = ii * 256 + tid;
                    sH[idx] = __ldcg(src + idx);
                }
                __syncthreads();
                gate_acc64(sW, sH, jj, b, e0, e1, e2, e3);
            }
            float hh = lstm_update(e0, e1, e2, e3, cH);
            sTmp[b * 4 + jj] = hh;
            __syncthreads();
            if (tid < 64)
                g_hap[((size_t)wph * 4 + 2 + dir) * 4096 + qc * 64 + tid] = *(float4*)&sTmp[tid * 4];
            __syncthreads();
            if (tid == 0) strel(&g_ahflag[cta], (unsigned)(t + 1));
        }
    }
}

// ---------------- fc1 ----------------
__global__ void fc1_kernel(const float* __restrict__ W1, const float* __restrict__ b1)
{
    __shared__ float4 sw4[4 * 256];
    int tid = threadIdx.x;
    int n0  = blockIdx.x * 4;
    const float4* W14 = (const float4*)W1;
    for (int i = tid; i < 1024; i += 256) {
        int r = i >> 8, k4 = i & 255;
        sw4[r * 256 + k4] = W14[(size_t)(n0 + r) * 256 + k4];
    }
    __syncthreads();
    int b = tid & 63, nn = tid >> 6;
    float acc = 0.f;
    #pragma unroll
    for (int scan = 0; scan < 4; scan++) {
        int ph = (scan < 2) ? 1 : 0;
        const float4* X = g_hap + ((size_t)ph * 4 + scan) * 4096;
        #pragma unroll 4
        for (int q = 0; q < 64; q++) {
            float4 xv = X[q * 64 + b];
            float4 wv = sw4[nn * 256 + scan * 64 + q];
            acc += xv.x * wv.x + xv.y * wv.y + xv.z * wv.z + xv.w * wv.w;
        }
    }
    int n = n0 + nn;
    g_y1[n * 64 + b] = tanhf(acc + b1[n]);
}

// ---------------- fc2 ----------------
__global__ void fc2_kernel(const float* __restrict__ W2, const float* __restrict__ b2,
                           float* __restrict__ out)
{
    int nc = blockIdx.x;
    int b  = threadIdx.x;
    float acc = 0.f;
    #pragma unroll 8
    for (int n = 0; n < 512; n++) acc += g_y1[n * 64 + b] * W2[nc * 512 + n];
    out[b * NCLS + nc] = acc + b2[nc];
}

extern "C" void kernel_launch(void* const* d_in, const int* in_sizes, int n_in,
                              void* d_out, int out_size)
{
    const int*   text  = (const int*)d_in[0];
    const int*   label = (const int*)d_in[1];
    const float* emb   = (const float*)d_in[2];
    const float* cWihf = (const float*)d_in[3],  *cWhhf = (const float*)d_in[4];
    const float* cbihf = (const float*)d_in[5],  *cbhhf = (const float*)d_in[6];
    const float* cWihb = (const float*)d_in[7],  *cWhhb = (const float*)d_in[8];
    const float* cbihb = (const float*)d_in[9],  *cbhhb = (const float*)d_in[10];
    const float* mpw1  = (const float*)d_in[11], *mpw2  = (const float*)d_in[12];
    const float* aWihf = (const float*)d_in[13], *aWhhf = (const float*)d_in[14];
    const float* abihf = (const float*)d_in[15], *abhhf = (const float*)d_in[16];
    const float* aWihb = (const float*)d_in[17], *aWhhb = (const float*)d_in[18];
    const float* abihb = (const float*)d_in[19], *abhhb = (const float*)d_in[20];
    const float* W1    = (const float*)d_in[21], *b1    = (const float*)d_in[22];
    const float* W2    = (const float*)d_in[23], *b2    = (const float*)d_in[24];
    float* out = (float*)d_out;

    const int smem_gat  = 256 * 65 * 4;                  //  66560 B
    const int smem_scan = (256 + 4096) * 4 + 4096 * 16;  //  82944 B (covers xproj's 64KB too)
    cudaFuncSetAttribute(gather_kernel, cudaFuncAttributeMaxDynamicSharedMemorySize, smem_gat);
    cudaFuncSetAttribute(ctx_fused,     cudaFuncAttributeMaxDynamicSharedMemorySize, smem_scan);
    cudaFuncSetAttribute(agg_scan,      cudaFuncAttributeMaxDynamicSharedMemorySize, smem_scan);

    gather_kernel<<<TT + TL, 256, smem_gat>>>(text, label, emb);
    ctx_fused<<<256, 256, smem_scan>>>(cWihf, cWihb,
        cWhhf, cbihf, cbhhf, cWhhb, cbihb, cbhhb);
    match_kernel<<<144, 256>>>(mpw1, mpw2);
    agg_scan<<<128, 256, smem_scan>>>(
        aWihf, aWhhf, abihf, abhhf, aWihb, aWhhb, abihb, abhhb);
    fc1_kernel<<<128, 256>>>(W1, b1);
    fc2_kernel<<<20, 64>>>(W2, b2, out);
}

// round 16
// speedup vs baseline: 1.0313x; 1.0313x over previous
#include <cuda_runtime.h>
#include <math.h>

#define BB   64
#define HH   256
#define TT   512
#define TL   64
#define NCLS 20
#define NSLOT 576   // 512 text + 64 label time slots

// ---------------- device state ----------------
// float4 [t][k-quad][b] layouts
__device__ float4 g_xt[TT*64*64];    // text  x
__device__ float4 g_xl[TL*64*64];    // label x
__device__ float4 g_hpf[TT*64*64];   // premise fw h
__device__ float4 g_hpb[TT*64*64];
__device__ float4 g_hlf[TL*64*64];
__device__ float4 g_hlb[TL*64*64];
__device__ float4 g_hap[3*4*64*64];  // agg h mod-3: [phase][scan][q][b]
__device__ float  g_xp[(size_t)2*NSLOT*1024*64];  // x@Wih^T: [dir][slot][gaterow][b]
__device__ float  g_mvp[TT*2*64];    // [t][persp][b]
__device__ float  g_mvh[TL*2*64];
__device__ float  g_y1[512*64];      // [n][b]
__device__ unsigned g_cflag[128];    // ctx text h flags
__device__ unsigned g_clflag[128];   // ctx label h flags
__device__ unsigned g_apflag[128];   // agg premise h flags
__device__ unsigned g_ahflag[128];   // agg hyp h flags

__device__ __forceinline__ float sigf(float x) { return 1.f / (1.f + __expf(-x)); }

__device__ __forceinline__ unsigned ldacq(const unsigned* p) {
    unsigned v;
    asm volatile("ld.acquire.gpu.u32 %0, [%1];" : "=r"(v) : "l"(p) : "memory");
    return v;
}
__device__ __forceinline__ void strel(unsigned* p, unsigned v) {
    asm volatile("st.release.gpu.u32 [%0], %1;" :: "l"(p), "r"(v) : "memory");
}

__device__ __forceinline__ float lstm_update(float a0, float a1, float a2, float a3, float &c)
{
    float ig = sigf(a0), fg = sigf(a1), gv = tanhf(a2), og = sigf(a3);
    c = fg * c + ig * gv;
    return og * tanhf(c);
}

// accumulate 4 gates over 64 k-quads; sW rows stride 256; sX [q][b] float4.
// warp-uniform jj -> weight LDS broadcast (1 wf); b spans warp -> x LDS 4 wf.
__device__ __forceinline__ void gate_acc64(const float* __restrict__ sW,
                                           const float4* __restrict__ sX,
                                           int jj, int b,
                                           float &a0, float &a1, float &a2, float &a3)
{
    const float* w0 = sW + (jj * 4 + 0) * 256;
    const float* w1 = sW + (jj * 4 + 1) * 256;
    const float* w2 = sW + (jj * 4 + 2) * 256;
    const float* w3 = sW + (jj * 4 + 3) * 256;
    #pragma unroll 4
    for (int q = 0; q < 64; q++) {
        float4 x  = sX[q * 64 + b];
        float4 v0 = *(const float4*)(w0 + q * 4);
        float4 v1 = *(const float4*)(w1 + q * 4);
        float4 v2 = *(const float4*)(w2 + q * 4);
        float4 v3 = *(const float4*)(w3 + q * 4);
        a0 += v0.x * x.x + v0.y * x.y + v0.z * x.z + v0.w * x.w;
        a1 += v1.x * x.x + v1.y * x.y + v1.z * x.z + v1.w * x.w;
        a2 += v2.x * x.x + v2.y * x.y + v2.z * x.z + v2.w * x.w;
        a3 += v3.x * x.x + v3.y * x.y + v3.z * x.z + v3.w * x.w;
    }
}

// ---------------- init: zero flags (each replay) ----------------
__global__ void init_kernel()
{
    int i = threadIdx.x;
    if (i < 128) { g_cflag[i] = 0u; g_clflag[i] = 0u; g_apflag[i] = 0u; g_ahflag[i] = 0u; }
}

// ---------------- gather x = emb[tokens] into packed [t][q][b] ----------------
__global__ void gather_kernel(const int* __restrict__ text, const int* __restrict__ label,
                              const float* __restrict__ emb)
{
    extern __shared__ float sS[];   // [256][65]
    int tt  = blockIdx.x;
    int tid = threadIdx.x, w = tid >> 5, l = tid & 31;
    const int* toks; int T, t; float4* dst;
    if (tt < TT) { toks = text;  T = TT; t = tt;      dst = g_xt; }
    else         { toks = label; T = TL; t = tt - TT; dst = g_xl; }

    for (int bt = w; bt < 64; bt += 8) {
        int tok = toks[bt * T + t];
        const float4* row = (const float4*)(emb + (size_t)tok * 256);
        float4 v0 = row[l], v1 = row[l + 32];
        int k0 = l * 4, k1 = (l + 32) * 4;
        sS[(k0 + 0) * 65 + bt] = v0.x; sS[(k0 + 1) * 65 + bt] = v0.y;
        sS[(k0 + 2) * 65 + bt] = v0.z; sS[(k0 + 3) * 65 + bt] = v0.w;
        sS[(k1 + 0) * 65 + bt] = v1.x; sS[(k1 + 1) * 65 + bt] = v1.y;
        sS[(k1 + 2) * 65 + bt] = v1.z; sS[(k1 + 3) * 65 + bt] = v1.w;
    }
    __syncthreads();
    #pragma unroll
    for (int ii = 0; ii < 16; ii++) {
        int idx = ii * 256 + tid;
        int q = idx >> 6, b = idx & 63;
        float4 o = make_float4(sS[(4*q + 0) * 65 + b], sS[(4*q + 1) * 65 + b],
                               sS[(4*q + 2) * 65 + b], sS[(4*q + 3) * 65 + b]);
        dst[((size_t)t * 64 + q) * 64 + b] = o;
    }
}

// ---------------- xproj: g_xp[dir][slot][gr][b] = sum_k Wih[gr][k] * x[slot][k][b] ----------------
// grid = 2 dirs * 576 slots * 16 row-tiles = 18432. block 256 = 64 b x 4 jj; thread does 16 rows.
// x read directly through L1 (same [kq][b] addrs across the 4 jj groups -> L1 reuse).
// smem = W tile only (64KB) -> 3 blocks/SM, wave-overlapped staging.
__global__ __launch_bounds__(256) void xproj_kernel(
    const float* __restrict__ Wih_f, const float* __restrict__ Wih_b)
{
    extern __shared__ float sWp[];         // [64 rows][256 k]

    int bid = blockIdx.x;
    int dir = bid / 9216;
    int rem = bid - dir * 9216;
    int slot  = rem >> 4;
    int rtile = rem & 15;
    const float* W = dir ? Wih_b : Wih_f;

    int tid = threadIdx.x, b = tid & 63, jj = tid >> 6;

    #pragma unroll
    for (int ii = 0; ii < 16; ii++) {            // stage W tile: 64 rows x 256 k
        int idx = ii * 256 + tid;                // 4096 float4 cells
        int r = idx >> 6, k4 = idx & 63;
        *(float4*)&sWp[r * 256 + k4 * 4] =
            *(const float4*)&W[(size_t)(rtile * 64 + r) * 256 + k4 * 4];
    }
    __syncthreads();

    const float4* xs = (slot < TT) ? (g_xt + (size_t)slot * 4096)
                                   : (g_xl + (size_t)(slot - TT) * 4096);

    float acc[16];
    #pragma unroll
    for (int i = 0; i < 16; i++) acc[i] = 0.f;
    const float* wb = sWp + (jj * 16) * 256;
    #pragma unroll 4
    for (int kq = 0; kq < 64; kq++) {
        float4 x = __ldg(&xs[kq * 64 + b]);
        #pragma unroll
        for (int i = 0; i < 16; i++) {
            float4 w = *(const float4*)(wb + i * 256 + kq * 4);
            acc[i] += w.x * x.x + w.y * x.y + w.z * x.z + w.w * x.w;
        }
    }
    size_t base = ((size_t)(dir * NSLOT + slot) * 1024 + rtile * 64 + jj * 16) * 64 + b;
    #pragma unroll
    for (int i = 0; i < 16; i++) g_xp[base + (size_t)i * 64] = acc[i];
}

// ---------------- persistent context scan (h-GEMV only; x-proj precomputed) ----------------
// 128 CTAs: dir = cta>>6, quad qc = cta&63. 256 threads = 64 b x 4 jj.
__global__ __launch_bounds__(256, 1) void ctx_scan(
    const float* __restrict__ Whh_f, const float* __restrict__ bih_f, const float* __restrict__ bhh_f,
    const float* __restrict__ Whh_b, const float* __restrict__ bih_b, const float* __restrict__ bhh_b)
{
    extern __shared__ float sm[];
    float*  sTmp = sm;                           // 256
    float*  sW   = sm + 256;                     // [16][256]
    float4* sH   = (float4*)(sm + 256 + 4096);   // [64 q][64 b]

    int cta = blockIdx.x, dir = cta >> 6, qc = cta & 63, j0 = qc * 4;
    const float* Whh = dir ? Whh_b : Whh_f;
    const float* bih = dir ? bih_b : bih_f;
    const float* bhh = dir ? bhh_b : bhh_f;
    float4* hT = dir ? g_hpb : g_hpf;
    float4* hL = dir ? g_hlb : g_hlf;

    int tid = threadIdx.x, b = tid & 63, jj = tid >> 6, j = j0 + jj;

    for (int i = tid; i < 1024; i += 256) {      // stage Whh slice once
        int r = i >> 6, k = (i & 63) * 4;
        int gr = (r & 3) * 256 + j0 + (r >> 2);
        *(float4*)&sW[r * 256 + k] = *(const float4*)&Whh[(size_t)gr * 256 + k];
    }
    float bb0 = bih[j]       + bhh[j];
    float bb1 = bih[256 + j] + bhh[256 + j];
    float bb2 = bih[512 + j] + bhh[512 + j];
    float bb3 = bih[768 + j] + bhh[768 + j];

    float cT = 0.f, cL = 0.f;
    const size_t xpd = (size_t)dir * NSLOT * 65536;   // 1024*64 per slot

    for (int t = 0; t < TT; t++) {
        // ---- text ----
        int pos = dir ? (TT - 1 - t) : t;
        size_t xb = xpd + (size_t)pos * 65536;
        float xp0 = g_xp[xb + (size_t)(j      ) * 64 + b];
        float xp1 = g_xp[xb + (size_t)(256 + j) * 64 + b];
        float xp2 = g_xp[xb + (size_t)(512 + j) * 64 + b];
        float xp3 = g_xp[xb + (size_t)(768 + j) * 64 + b];
        if (t > 0 && tid < 64) {
            const unsigned* f = &g_cflag[dir * 64 + tid];
            while (ldacq(f) < (unsigned)t) { }
        }
        __syncthreads();
        float a0 = xp0 + bb0, a1 = xp1 + bb1, a2 = xp2 + bb2, a3 = xp3 + bb3;
        if (t > 0) {
            int pp = dir ? pos + 1 : pos - 1;
            const float4* src = hT + (size_t)pp * 4096;
            #pragma unroll
            for (int ii = 0; ii < 16; ii++) { int idx = ii * 256 + tid; sH[idx] = src[idx]; }
            __syncthreads();
            gate_acc64(sW, sH, jj, b, a0, a1, a2, a3);
        }
        float h = lstm_update(a0, a1, a2, a3, cT);
        sTmp[b * 4 + jj] = h;
        __syncthreads();
        if (tid < 64) hT[(size_t)pos * 4096 + qc * 64 + tid] = *(float4*)&sTmp[tid * 4];
        __syncthreads();
        if (tid == 0) strel(&g_cflag[cta], (unsigned)(t + 1));

        // ---- label rides along (t < TL) ----
        if (t < TL) {
            int posL = dir ? (TL - 1 - t) : t;
            size_t xbl = xpd + (size_t)(TT + posL) * 65536;
            float y0 = g_xp[xbl + (size_t)(j      ) * 64 + b];
            float y1 = g_xp[xbl + (size_t)(256 + j) * 64 + b];
            float y2 = g_xp[xbl + (size_t)(512 + j) * 64 + b];
            float y3 = g_xp[xbl + (size_t)(768 + j) * 64 + b];
            if (t > 0 && tid < 64) {
                const unsigned* f = &g_clflag[dir * 64 + tid];
                while (ldacq(f) < (unsigned)t) { }
            }
            __syncthreads();
            float e0 = y0 + bb0, e1 = y1 + bb1, e2 = y2 + bb2, e3 = y3 + bb3;
            if (t > 0) {
                int ppL = dir ? posL + 1 : posL - 1;
                const float4* src = hL + (size_t)ppL * 4096;
                #pragma unroll
                for (int ii = 0; ii < 16; ii++) { int idx = ii * 256 + tid; sH[idx] = src[idx]; }
                __syncthreads();
                gate_acc64(sW, sH, jj, b, e0, e1, e2, e3);
            }
            float hh = lstm_update(e0, e1, e2, e3, cL);
            sTmp[b * 4 + jj] = hh;
            __syncthreads();
            if (tid < 64) hL[(size_t)posL * 4096 + qc * 64 + tid] = *(float4*)&sTmp[tid * 4];
            __syncthreads();
            if (tid == 0) strel(&g_clflag[cta], (unsigned)(t + 1));
        }
    }
}

// ---------------- multi-perspective match (L = 1), 4 slots per block ----------------
__global__ void match_kernel(const float* __restrict__ w1, const float* __restrict__ w2)
{
    int tid = threadIdx.x;
    int b   = tid & 63;
    int bi  = blockIdx.x * 4 + (tid >> 6);   // slot 0..575
    const float4 *v1f, *v2f, *v1b, *v2b;
    float* outp;
    if (bi < TT) {
        int t = bi;
        v1f = g_hpf + (size_t)t * 4096;
        v2f = g_hlf + (size_t)(TL - 1) * 4096;
        v1b = g_hpb + (size_t)t * 4096;
        v2b = g_hlb;
        outp = g_mvp + (size_t)t * 2 * 64;
    } else {
        int t = bi - TT;
        v1f = g_hlf + (size_t)t * 4096;
        v2f = g_hpf + (size_t)(TT - 1) * 4096;
        v1b = g_hlb + (size_t)t * 4096;
        v2b = g_hpb;
        outp = g_mvh + (size_t)t * 2 * 64;
    }
    const float4* w14 = (const float4*)w1;
    const float4* w24 = (const float4*)w2;
    float n1 = 0, da = 0, db = 0, n2 = 0, ea = 0, eb = 0;
    for (int q = 0; q < 64; q++) {
        float4 wv = w14[q];
        float4 p = v1f[q * 64 + b], qq = v2f[q * 64 + b];
        float w2x = wv.x*wv.x, w2y = wv.y*wv.y, w2z = wv.z*wv.z, w2w = wv.w*wv.w;
        n1 += w2x*p.x*qq.x + w2y*p.y*qq.y + w2z*p.z*qq.z + w2w*p.w*qq.w;
        da += w2x*p.x*p.x  + w2y*p.y*p.y  + w2z*p.z*p.z  + w2w*p.w*p.w;
        db += w2x*qq.x*qq.x+ w2y*qq.y*qq.y+ w2z*qq.z*qq.z+ w2w*qq.w*qq.w;
        float4 uv = w24[q];
        float4 r = v1b[q * 64 + b], s = v2b[q * 64 + b];
        float u2x = uv.x*uv.x, u2y = uv.y*uv.y, u2z = uv.z*uv.z, u2w = uv.w*uv.w;
        n2 += u2x*r.x*s.x + u2y*r.y*s.y + u2z*r.z*s.z + u2w*r.w*s.w;
        ea += u2x*r.x*r.x + u2y*r.y*r.y + u2z*r.z*r.z + u2w*r.w*r.w;
        eb += u2x*s.x*s.x + u2y*s.y*s.y + u2z*s.z*s.z + u2w*s.w*s.w;
    }
    outp[b]      = n1 / fmaxf(sqrtf(da) * sqrtf(db), 1e-8f);
    outp[64 + b] = n2 / fmaxf(sqrtf(ea) * sqrtf(eb), 1e-8f);
}

// ---------------- persistent aggregation scan (premise + hyp rides t<64) ----------------
__global__ __launch_bounds__(256, 1) void agg_scan(
    const float* __restrict__ Wih_f, const float* __restrict__ Whh_f,
    const float* __restrict__ bih_f, const float* __restrict__ bhh_f,
    const float* __restrict__ Wih_b, const float* __restrict__ Whh_b,
    const float* __restrict__ bih_b, const float* __restrict__ bhh_b)
{
    extern __shared__ float sm[];
    float*  sTmp = sm;                           // 256
    float*  sW   = sm + 256;                     // [16][256]
    float4* sH   = (float4*)(sm + 256 + 4096);   // [64 q][64 b]

    int cta = blockIdx.x, dir = cta >> 6, qc = cta & 63, j0 = qc * 4;
    const float* Wih = dir ? Wih_b : Wih_f;
    const float* Whh = dir ? Whh_b : Whh_f;
    const float* bih = dir ? bih_b : bih_f;
    const float* bhh = dir ? bhh_b : bhh_f;

    int tid = threadIdx.x, b = tid & 63, jj = tid >> 6, j = j0 + jj;

    for (int i = tid; i < 1024; i += 256) {
        int r = i >> 6, k = (i & 63) * 4;
        int gr = (r & 3) * 256 + j0 + (r >> 2);
        *(float4*)&sW[r * 256 + k] = *(const float4*)&Whh[(size_t)gr * 256 + k];
    }
    int r0 = j, r1 = 256 + j, r2 = 512 + j, r3 = 768 + j;
    float bb0 = bih[r0] + bhh[r0], bb1 = bih[r1] + bhh[r1];
    float bb2 = bih[r2] + bhh[r2], bb3 = bih[r3] + bhh[r3];
    float wi00 = Wih[r0*2], wi01 = Wih[r0*2+1];
    float wi10 = Wih[r1*2], wi11 = Wih[r1*2+1];
    float wi20 = Wih[r2*2], wi21 = Wih[r2*2+1];
    float wi30 = Wih[r3*2], wi31 = Wih[r3*2+1];

    float cP = 0.f, cH = 0.f;

    for (int t = 0; t < TT; t++) {
        int wph = t % 3;
        int rph = (t + 2) % 3;

        // ---- premise ----
        int pos = dir ? (TT - 1 - t) : t;
        const float* mv = g_mvp + (size_t)pos * 2 * 64;
        float m0 = mv[b], m1 = mv[64 + b];
        if (t > 0 && tid < 64) {
            const unsigned* f = &g_apflag[dir * 64 + tid];
            while (ldacq(f) < (unsigned)t) { }
        }
        __syncthreads();
        float a0 = bb0 + m0 * wi00 + m1 * wi01;
        float a1 = bb1 + m0 * wi10 + m1 * wi11;
        float a2 = bb2 + m0 * wi20 + m1 * wi21;
        float a3 = bb3 + m0 * wi30 + m1 * wi31;
        if (t > 0) {
            const float4* src = g_hap + ((size_t)rph * 4 + dir) * 4096;
            #pragma unroll
            for (int ii = 0; ii < 16; ii++) {
                int idx = ii * 256 + tid;
                sH[idx] = __ldcg(src + idx);   // addrs recur mod 3 -> bypass L1
            }
            __syncthreads();
            gate_acc64(sW, sH, jj, b, a0, a1, a2, a3);
        }
        float h = lstm_update(a0, a1, a2, a3, cP);
        sTmp[b * 4 + jj] = h;
        __syncthreads();
        if (tid < 64)
            g_hap[((size_t)wph * 4 + dir) * 4096 + qc * 64 + tid] = *(float4*)&sTmp[tid * 4];
        __syncthreads();
        if (tid == 0) strel(&g_apflag[cta], (unsigned)(t + 1));

        // ---- hyp (t < TL) ----
        if (t < TL) {
            int posH = dir ? (TL - 1 - t) : t;
            const float* mvh = g_mvh + (size_t)posH * 2 * 64;
            float n0 = mvh[b], n1v = mvh[64 + b];
            if (t > 0 && tid < 64) {
                const unsigned* f = &g_ahflag[dir * 64 + tid];
                while (ldacq(f) < (unsigned)t) { }
            }
            __syncthreads();
            float e0 = bb0 + n0 * wi00 + n1v * wi01;
            float e1 = bb1 + n0 * wi10 + n1v * wi11;
            float e2 = bb2 + n0 * wi20 + n1v * wi21;
            float e3 = bb3 + n0 * wi30 + n1v * wi31;
            if (t > 0) {
                const float4* src = g_hap + ((size_t)rph * 4 + 2 + dir) * 4096;
                #pragma unroll
                for (int ii = 0; ii < 16; ii++) {
                    int idx = ii * 256 + tid;
                    sH[idx] = __ldcg(src + idx);
                }
                __syncthreads();
                gate_acc64(sW, sH, jj, b, e0, e1, e2, e3);
            }
            float hh = lstm_update(e0, e1, e2, e3, cH);
            sTmp[b * 4 + jj] = hh;
            __syncthreads();
            if (tid < 64)
                g_hap[((size_t)wph * 4 + 2 + dir) * 4096 + qc * 64 + tid] = *(float4*)&sTmp[tid * 4];
            __syncthreads();
            if (tid == 0) strel(&g_ahflag[cta], (unsigned)(t + 1));
        }
    }
}

// ---------------- fc1: tanh(x @ W1^T + b1) ----------------
// premise final at phase 511%3=1 (scans 0,1); hyp final at phase 63%3=0 (scans 2,3).
__global__ void fc1_kernel(const float* __restrict__ W1, const float* __restrict__ b1)
{
    __shared__ float4 sw4[4 * 256];
    int tid = threadIdx.x;
    int n0  = blockIdx.x * 4;
    const float4* W14 = (const float4*)W1;
    for (int i = tid; i < 1024; i += 256) {
        int r = i >> 8, k4 = i & 255;
        sw4[r * 256 + k4] = W14[(size_t)(n0 + r) * 256 + k4];
    }
    __syncthreads();
    int b = tid & 63, nn = tid >> 6;
    float acc = 0.f;
    #pragma unroll
    for (int scan = 0; scan < 4; scan++) {
        int ph = (scan < 2) ? 1 : 0;
        const float4* X = g_hap + ((size_t)ph * 4 + scan) * 4096;
        #pragma unroll 4
        for (int q = 0; q < 64; q++) {
            float4 xv = X[q * 64 + b];
            float4 wv = sw4[nn * 256 + scan * 64 + q];
            acc += xv.x * wv.x + xv.y * wv.y + xv.z * wv.z + xv.w * wv.w;
        }
    }
    int n = n0 + nn;
    g_y1[n * 64 + b] = tanhf(acc + b1[n]);
}

// ---------------- fc2 ----------------
__global__ void fc2_kernel(const float* __restrict__ W2, const float* __restrict__ b2,
                           float* __restrict__ out)
{
    int nc = blockIdx.x;    // 20
    int b  = threadIdx.x;   // 64
    float acc = 0.f;
    #pragma unroll 8
    for (int n = 0; n < 512; n++) acc += g_y1[n * 64 + b] * W2[nc * 512 + n];
    out[b * NCLS + nc] = acc + b2[nc];
}

extern "C" void kernel_launch(void* const* d_in, const int* in_sizes, int n_in,
                              void* d_out, int out_size)
{
    const int*   text  = (const int*)d_in[0];
    const int*   label = (const int*)d_in[1];
    const float* emb   = (const float*)d_in[2];
    const float* cWihf = (const float*)d_in[3],  *cWhhf = (const float*)d_in[4];
    const float* cbihf = (const float*)d_in[5],  *cbhhf = (const float*)d_in[6];
    const float* cWihb = (const float*)d_in[7],  *cWhhb = (const float*)d_in[8];
    const float* cbihb = (const float*)d_in[9],  *cbhhb = (const float*)d_in[10];
    const float* mpw1  = (const float*)d_in[11], *mpw2  = (const float*)d_in[12];
    const float* aWihf = (const float*)d_in[13], *aWhhf = (const float*)d_in[14];
    const float* abihf = (const float*)d_in[15], *abhhf = (const float*)d_in[16];
    const float* aWihb = (const float*)d_in[17], *aWhhb = (const float*)d_in[18];
    const float* abihb = (const float*)d_in[19], *abhhb = (const float*)d_in[20];
    const float* W1    = (const float*)d_in[21], *b1    = (const float*)d_in[22];
    const float* W2    = (const float*)d_in[23], *b2    = (const float*)d_in[24];
    float* out = (float*)d_out;

    const int smem_gat  = 256 * 65 * 4;                  //  66560 B
    const int smem_xprj = 16384 * 4;                     //  65536 B (W tile only)
    const int smem_scan = (256 + 4096) * 4 + 4096 * 16;  //  82944 B
    cudaFuncSetAttribute(gather_kernel, cudaFuncAttributeMaxDynamicSharedMemorySize, smem_gat);
    cudaFuncSetAttribute(xproj_kernel,  cudaFuncAttributeMaxDynamicSharedMemorySize, smem_xprj);
    cudaFuncSetAttribute(ctx_scan,      cudaFuncAttributeMaxDynamicSharedMemorySize, smem_scan);
    cudaFuncSetAttribute(agg_scan,      cudaFuncAttributeMaxDynamicSharedMemorySize, smem_scan);

    init_kernel<<<1, 128>>>();
    gather_kernel<<<TT + TL, 256, smem_gat>>>(text, label, emb);
    xproj_kernel<<<2 * NSLOT * 16, 256, smem_xprj>>>(cWihf, cWihb);
    ctx_scan<<<128, 256, smem_scan>>>(cWhhf, cbihf, cbhhf, cWhhb, cbihb, cbhhb);
    match_kernel<<<144, 256>>>(mpw1, mpw2);
    agg_scan<<<128, 256, smem_scan>>>(
        aWihf, aWhhf, abihf, abhhf, aWihb, aWhhb, abihb, abhhb);
    fc1_kernel<<<128, 256>>>(W1, b1);
    fc2_kernel<<<20, 64>>>(W2, b2, out);
}